// round 6
// baseline (speedup 1.0000x reference)
#include <cuda_runtime.h>
#include <cuda_bf16.h>
#include <cstdint>

#define IMG 1024
#define EMBED 2700

// device scratch (no cudaMalloc allowed)
__device__ float d_boxes_px[2 * 2 * 100 * 4];   // [view][batch][slot][xyxy px]
__device__ float d_t [2 * 200 * EMBED];         // [view][row][e]
__device__ float d_gt[2 * 200 * EMBED];         // after Linear
__device__ float d_sim[2 * 100 * 100];

// ---------- Stage 1: top-100 + box gather (bitonic sort of 8192) ----------
__global__ void __launch_bounds__(1024) topk_kernel(
    const float* __restrict__ gl, const float* __restrict__ al,
    const float* __restrict__ gbx, const float* __restrict__ abx)
{
    int b = blockIdx.x, v = blockIdx.y;
    const float* logits = (v ? al : gl) + b * 6000;
    const float* boxes  = (v ? abx : gbx) + b * 300 * 4;

    __shared__ unsigned int   sk[8192];
    __shared__ unsigned short si[8192];
    int tid = threadIdx.x;

    for (int i = tid; i < 8192; i += 1024) {
        unsigned int key = 0xFFFFFFFFu; unsigned short idx = 0xFFFFu;
        if (i < 6000) {
            float p = 1.0f / (1.0f + expf(-logits[i]));
            unsigned int u = __float_as_uint(p);
            u ^= (u & 0x80000000u) ? 0xFFFFFFFFu : 0x80000000u;
            key = ~u;                      // ascending key == descending prob
            idx = (unsigned short)i;
        }
        sk[i] = key; si[i] = idx;
    }
    __syncthreads();

    for (int k = 2; k <= 8192; k <<= 1)
        for (int j = k >> 1; j > 0; j >>= 1) {
            for (int i = tid; i < 8192; i += 1024) {
                int ixj = i ^ j;
                if (ixj > i) {
                    unsigned int   ka = sk[i], kb = sk[ixj];
                    unsigned short ia = si[i], ib = si[ixj];
                    bool agtb = (ka > kb) || (ka == kb && ia > ib);
                    if (agtb == ((i & k) == 0)) {
                        sk[i] = kb; sk[ixj] = ka; si[i] = ib; si[ixj] = ia;
                    }
                }
            }
            __syncthreads();
        }

    if (tid < 100) {
        int q = (int)si[tid] / 20;
        float cx = boxes[q*4+0], cy = boxes[q*4+1];
        float w  = boxes[q*4+2], h  = boxes[q*4+3];
        float* o = &d_boxes_px[((v*2 + b)*100 + tid)*4];
        o[0] = (cx - 0.5f*w) * 1024.0f;  o[1] = (cy - 0.5f*h) * 1024.0f;
        o[2] = (cx + 0.5f*w) * 1024.0f;  o[3] = (cy + 0.5f*h) * 1024.0f;
    }
}

// ---------- Stage 2: ROI bilinear 30x30 + interleave + pos_enc ----------
// row m of the [200, 2700] matrix per view: patch(b=m%2, k=m/2) + pos_enc[m%100]
__global__ void __launch_bounds__(256) roi_kernel(
    const float* __restrict__ g_img, const float* __restrict__ a_img,
    const float* __restrict__ pos_enc)
{
    int m = blockIdx.x, v = blockIdx.y;
    const float* img = v ? a_img : g_img;
    int b = m & 1, kslot = m >> 1, k2 = m % 100;
    int tid = threadIdx.x;

    const float* bx = &d_boxes_px[((v*2 + b)*100 + kslot)*4];
    float x0 = rintf(bx[0]), y0 = rintf(bx[1]);
    float x1 = rintf(bx[2]), y1 = rintf(bx[3]);
    float w = x1 - x0, h = y1 - y0;
    bool valid = (w > 0.0f) && (h > 0.0f);

    __shared__ int   iy0[30], iy1[30], ix0[30], ix1[30];
    __shared__ float fwy[30], fwx[30];
    if (tid < 30) {
        float g = (float)tid + 0.5f;
        float sy = fminf(fmaxf(g * h / 30.0f - 0.5f, 0.0f), fmaxf(h - 1.0f, 0.0f));
        float ay = y0 + sy, yf = floorf(ay);
        fwy[tid] = ay - yf;
        iy0[tid] = (int)fminf(fmaxf(yf,        0.0f), 1023.0f);
        iy1[tid] = (int)fminf(fmaxf(yf + 1.0f, 0.0f), 1023.0f);
        float sx = fminf(fmaxf(g * w / 30.0f - 0.5f, 0.0f), fmaxf(w - 1.0f, 0.0f));
        float ax = x0 + sx, xf = floorf(ax);
        fwx[tid] = ax - xf;
        ix0[tid] = (int)fminf(fmaxf(xf,        0.0f), 1023.0f);
        ix1[tid] = (int)fminf(fmaxf(xf + 1.0f, 0.0f), 1023.0f);
    }
    __syncthreads();

    float* trow = &d_t[((size_t)(v*200 + m)) * EMBED];
    const float* pe = &pos_enc[(size_t)k2 * EMBED];
    for (int e = tid; e < EMBED; e += 256) {
        float val = 0.0f;
        if (valid) {
            int c = e / 900, r = e - c*900, py = r / 30, px = r - py*30;
            const float* ip = img + ((size_t)(b*3 + c) << 20);
            float wy = fwy[py], wx = fwx[px];
            const float* r0p = ip + iy0[py]*IMG;
            const float* r1p = ip + iy1[py]*IMG;
            float v00 = r0p[ix0[px]], v01 = r0p[ix1[px]];
            float v10 = r1p[ix0[px]], v11 = r1p[ix1[px]];
            float top = v00*(1.0f-wx) + v01*wx;
            float bot = v10*(1.0f-wx) + v11*wx;
            val = top*(1.0f-wy) + bot*wy;
        }
        trow[e] = val + pe[e];
    }
}

// ---------- Stage 3: gt = t @ W^T, M=200 N=2700 K=2700, FFMA2 ----------
__global__ void __launch_bounds__(256) gemm_kernel(
    const float* __restrict__ Wg, const float* __restrict__ Wa)
{
    const int v = blockIdx.z;
    const float* __restrict__ A = d_t  + (size_t)v * 200 * EMBED;
    const float* __restrict__ B = v ? Wa : Wg;        // [2700][2700] row=n, col=k
    float* __restrict__ C = d_gt + (size_t)v * 200 * EMBED;

    const int row0 = blockIdx.y * 64;
    const int col0 = blockIdx.x * 128;

    __shared__ float As[64][33];
    __shared__ __align__(16) float Bs[32][130];

    int tid = threadIdx.x;
    int tx = tid & 15, ty = tid >> 4;

    unsigned long long acc[4][4];
#pragma unroll
    for (int i = 0; i < 4; i++)
#pragma unroll
        for (int p = 0; p < 4; p++) acc[i][p] = 0ull;

    float aReg[8], bReg[16];

    auto loadTile = [&](int k0) {
#pragma unroll
        for (int l = 0; l < 8; l++) {
            int idx = tid + l*256; int r = idx >> 5, kk = idx & 31;
            int gr = row0 + r, gk = k0 + kk;
            aReg[l] = (gr < 200 && gk < EMBED) ? A[(size_t)gr*EMBED + gk] : 0.0f;
        }
#pragma unroll
        for (int l = 0; l < 16; l++) {
            int idx = tid + l*256; int r = idx >> 5, kk = idx & 31;
            int gr = col0 + r, gk = k0 + kk;
            bReg[l] = (gr < EMBED && gk < EMBED) ? B[(size_t)gr*EMBED + gk] : 0.0f;
        }
    };
    auto storeTile = [&]() {
#pragma unroll
        for (int l = 0; l < 8; l++) {
            int idx = tid + l*256;
            As[idx >> 5][idx & 31] = aReg[l];
        }
#pragma unroll
        for (int l = 0; l < 16; l++) {
            int idx = tid + l*256;
            Bs[idx & 31][idx >> 5] = bReg[l];    // Bs[k][col]
        }
    };

    loadTile(0); storeTile(); __syncthreads();

    const int NT = (EMBED + 31) / 32;  // 85
    for (int t = 0; t < NT; t++) {
        if (t + 1 < NT) loadTile((t + 1) * 32);
#pragma unroll 8
        for (int kk = 0; kk < 32; kk++) {
            unsigned long long bp[4];
#pragma unroll
            for (int p = 0; p < 4; p++)
                bp[p] = *reinterpret_cast<const unsigned long long*>(&Bs[kk][2*tx + 32*p]);
#pragma unroll
            for (int i = 0; i < 4; i++) {
                float a = As[ty + 16*i][kk];
                unsigned long long av;
                asm("mov.b64 %0, {%1, %1};" : "=l"(av) : "r"(__float_as_uint(a)));
#pragma unroll
                for (int p = 0; p < 4; p++)
                    asm("fma.rn.f32x2 %0, %1, %2, %0;"
                        : "+l"(acc[i][p]) : "l"(av), "l"(bp[p]));
            }
        }
        __syncthreads();
        if (t + 1 < NT) { storeTile(); __syncthreads(); }
    }

#pragma unroll
    for (int i = 0; i < 4; i++) {
        int gr = row0 + ty + 16*i;
        if (gr >= 200) continue;
#pragma unroll
        for (int p = 0; p < 4; p++) {
            int gc = col0 + 2*tx + 32*p;
            if (gc < EMBED) {
                float2 val;
                val.x = __uint_as_float((unsigned)(acc[i][p] & 0xffffffffu));
                val.y = __uint_as_float((unsigned)(acc[i][p] >> 32));
                *reinterpret_cast<float2*>(&C[(size_t)gr*EMBED + gc]) = val;
            }
        }
    }
}

// ---------- Stage 4: sim[b,q,k] = <gt[b,q], at[b,k]> / sqrt(384) ----------
__global__ void __launch_bounds__(256) sim_kernel()
{
    int b2 = blockIdx.y;
    int kbase = blockIdx.x * 4;
    __shared__ float arow[4][EMBED];          // 43.2 KB

    int tid = threadIdx.x;
    const float* at = d_gt + (size_t)200 * EMBED;   // aerial view
    for (int l = tid; l < 4*EMBED; l += 256) {
        int kk = l / EMBED, e = l - kk*EMBED;
        arow[kk][e] = at[(size_t)(b2*100 + kbase + kk)*EMBED + e];
    }
    __syncthreads();

    int w = tid >> 5, lane = tid & 31;
    const float rscale = 0.051031036307982884f;     // 1/sqrt(384)
    for (int q = w; q < 100; q += 8) {
        const float* g = &d_gt[(size_t)(b2*100 + q)*EMBED];
        float s0 = 0.f, s1 = 0.f, s2 = 0.f, s3 = 0.f;
        for (int e = lane; e < EMBED; e += 32) {
            float gv = g[e];
            s0 += gv * arow[0][e];  s1 += gv * arow[1][e];
            s2 += gv * arow[2][e];  s3 += gv * arow[3][e];
        }
#pragma unroll
        for (int off = 16; off > 0; off >>= 1) {
            s0 += __shfl_down_sync(0xffffffffu, s0, off);
            s1 += __shfl_down_sync(0xffffffffu, s1, off);
            s2 += __shfl_down_sync(0xffffffffu, s2, off);
            s3 += __shfl_down_sync(0xffffffffu, s3, off);
        }
        if (lane == 0) {
            float* o = &d_sim[(b2*100 + q)*100 + kbase];
            o[0] = s0*rscale; o[1] = s1*rscale; o[2] = s2*rscale; o[3] = s3*rscale;
        }
    }
}

// ---------- Stage 5: softmax over q (dim=1) per (b,k) ----------
__global__ void __launch_bounds__(128) softmax_kernel(float* __restrict__ out)
{
    int k = blockIdx.x, b2 = blockIdx.y, t = threadIdx.x;
    __shared__ float wr[4];
    __shared__ float bval;

    float v = (t < 100) ? d_sim[(b2*100 + t)*100 + k] : -3.4e38f;

    float m = v;
#pragma unroll
    for (int off = 16; off > 0; off >>= 1)
        m = fmaxf(m, __shfl_down_sync(0xffffffffu, m, off));
    if ((t & 31) == 0) wr[t >> 5] = m;
    __syncthreads();
    if (t == 0) bval = fmaxf(fmaxf(wr[0], wr[1]), fmaxf(wr[2], wr[3]));
    __syncthreads();
    float mx = bval;

    float e = (t < 100) ? expf(v - mx) : 0.0f;
    float s = e;
#pragma unroll
    for (int off = 16; off > 0; off >>= 1)
        s += __shfl_down_sync(0xffffffffu, s, off);
    if ((t & 31) == 0) wr[t >> 5] = s;
    __syncthreads();
    if (t == 0) bval = wr[0] + wr[1] + wr[2] + wr[3];
    __syncthreads();

    if (t < 100)
        out[(b2*100 + t)*100 + k] = e / bval;
}

// ---------- launch ----------
extern "C" void kernel_launch(void* const* d_in, const int* in_sizes, int n_in,
                              void* d_out, int out_size)
{
    const float* g_samples = (const float*)d_in[0];
    const float* a_samples = (const float*)d_in[1];
    const float* g_logits  = (const float*)d_in[2];
    const float* a_logits  = (const float*)d_in[3];
    const float* g_boxes   = (const float*)d_in[4];
    const float* a_boxes   = (const float*)d_in[5];
    const float* W_ground  = (const float*)d_in[6];
    const float* W_aerial  = (const float*)d_in[7];
    const float* pos_enc   = (const float*)d_in[8];
    float* out = (float*)d_out;

    topk_kernel<<<dim3(2, 2), 1024>>>(g_logits, a_logits, g_boxes, a_boxes);
    roi_kernel<<<dim3(200, 2), 256>>>(g_samples, a_samples, pos_enc);
    gemm_kernel<<<dim3(22, 4, 2), 256>>>(W_ground, W_aerial);
    sim_kernel<<<dim3(25, 2), 256>>>();
    softmax_kernel<<<dim3(100, 2), 128>>>(out);
}

// round 8
// speedup vs baseline: 1.5586x; 1.5586x over previous
#include <cuda_runtime.h>
#include <cuda_bf16.h>
#include <cstdint>

#define IMG 1024
#define EMBED 2700
#define ECH 54            // sim e-chunk (50 chunks * 54 = 2700)
#define NCH 50

// device scratch (no cudaMalloc allowed)
__device__ float d_boxes_px[2 * 2 * 100 * 4];   // [view][batch][slot][xyxy px]
__device__ float d_t [2 * 200 * EMBED];         // [view][row][e]
__device__ float d_gt[2 * 200 * EMBED];         // after Linear
__device__ float d_simp[NCH * 2 * 100 * 100];   // partial sims [ch][b][k][q]

// ---------- Stage 1: top-100 via histogram select + small bitonic ----------
__device__ __forceinline__ unsigned int prob_key(float x) {
    float p = 1.0f / (1.0f + expf(-x));
    return __float_as_uint(p);      // p in [0,1): positive floats compare as ints
}

__global__ void __launch_bounds__(1024) topk_kernel(
    const float* __restrict__ gl, const float* __restrict__ al,
    const float* __restrict__ gbx, const float* __restrict__ abx)
{
    int b = blockIdx.x, v = blockIdx.y;
    const float* logits = (v ? al : gl) + b * 6000;
    const float* boxes  = (v ? abx : gbx) + b * 300 * 4;
    int tid = threadIdx.x;

    __shared__ unsigned int hist[256];
    __shared__ int sT, scnt;
    __shared__ unsigned long long cand[4096];

    if (tid < 256) hist[tid] = 0u;
    __syncthreads();

    for (int i = tid; i < 6000; i += 1024)
        atomicAdd(&hist[prob_key(logits[i]) >> 22], 1u);
    __syncthreads();

    if (tid == 0) {
        unsigned int cum = 0; int T = 0;
        for (int bb = 255; bb >= 0; bb--) {
            cum += hist[bb];
            if (cum >= 100u) { T = bb; break; }
        }
        sT = T; scnt = 0;
    }
    __syncthreads();
    int T = sT;

    for (int i = tid; i < 6000; i += 1024) {
        unsigned int key = prob_key(logits[i]);
        if ((int)(key >> 22) >= T) {
            int pos = atomicAdd(&scnt, 1);
            if (pos < 4096)
                cand[pos] = (((unsigned long long)(0xFFFFFFFFu ^ key)) << 16)
                            | (unsigned long long)i;
        }
    }
    __syncthreads();

    int n = min(scnt, 4096);
    int n2 = 128;
    while (n2 < n) n2 <<= 1;

    for (int i = n + tid; i < n2; i += 1024) cand[i] = ~0ull;
    __syncthreads();

    for (int k = 2; k <= n2; k <<= 1)
        for (int j = k >> 1; j > 0; j >>= 1) {
            for (int i = tid; i < n2; i += 1024) {
                int ixj = i ^ j;
                if (ixj > i) {
                    unsigned long long a = cand[i], bb2 = cand[ixj];
                    bool up = ((i & k) == 0);
                    if ((a > bb2) == up) { cand[i] = bb2; cand[ixj] = a; }
                }
            }
            __syncthreads();
        }

    if (tid < 100) {
        int idx = (int)(cand[tid] & 0xFFFFull);
        int q = idx / 20;
        float cx = boxes[q*4+0], cy = boxes[q*4+1];
        float w  = boxes[q*4+2], h  = boxes[q*4+3];
        float* o = &d_boxes_px[((v*2 + b)*100 + tid)*4];
        o[0] = (cx - 0.5f*w) * 1024.0f;  o[1] = (cy - 0.5f*h) * 1024.0f;
        o[2] = (cx + 0.5f*w) * 1024.0f;  o[3] = (cy + 0.5f*h) * 1024.0f;
    }
}

// ---------- Stage 2: ROI bilinear 30x30 + interleave + pos_enc ----------
__global__ void __launch_bounds__(256) roi_kernel(
    const float* __restrict__ g_img, const float* __restrict__ a_img,
    const float* __restrict__ pos_enc)
{
    int m = blockIdx.x, v = blockIdx.y;
    const float* img = v ? a_img : g_img;
    int b = m & 1, kslot = m >> 1, k2 = m % 100;
    int tid = threadIdx.x;

    const float* bx = &d_boxes_px[((v*2 + b)*100 + kslot)*4];
    float x0 = rintf(bx[0]), y0 = rintf(bx[1]);
    float x1 = rintf(bx[2]), y1 = rintf(bx[3]);
    float w = x1 - x0, h = y1 - y0;
    bool valid = (w > 0.0f) && (h > 0.0f);

    __shared__ int   iy0[30], iy1[30], ix0[30], ix1[30];
    __shared__ float fwy[30], fwx[30];
    if (tid < 30) {
        float g = (float)tid + 0.5f;
        float sy = fminf(fmaxf(g * h / 30.0f - 0.5f, 0.0f), fmaxf(h - 1.0f, 0.0f));
        float ay = y0 + sy, yf = floorf(ay);
        fwy[tid] = ay - yf;
        iy0[tid] = (int)fminf(fmaxf(yf,        0.0f), 1023.0f);
        iy1[tid] = (int)fminf(fmaxf(yf + 1.0f, 0.0f), 1023.0f);
        float sx = fminf(fmaxf(g * w / 30.0f - 0.5f, 0.0f), fmaxf(w - 1.0f, 0.0f));
        float ax = x0 + sx, xf = floorf(ax);
        fwx[tid] = ax - xf;
        ix0[tid] = (int)fminf(fmaxf(xf,        0.0f), 1023.0f);
        ix1[tid] = (int)fminf(fmaxf(xf + 1.0f, 0.0f), 1023.0f);
    }
    __syncthreads();

    float* trow = &d_t[((size_t)(v*200 + m)) * EMBED];
    const float* pe = &pos_enc[(size_t)k2 * EMBED];
    for (int e = tid; e < EMBED; e += 256) {
        float val = 0.0f;
        if (valid) {
            int c = e / 900, r = e - c*900, py = r / 30, px = r - py*30;
            const float* ip = img + ((size_t)(b*3 + c) << 20);
            float wy = fwy[py], wx = fwx[px];
            const float* r0p = ip + iy0[py]*IMG;
            const float* r1p = ip + iy1[py]*IMG;
            float v00 = r0p[ix0[px]], v01 = r0p[ix1[px]];
            float v10 = r1p[ix0[px]], v11 = r1p[ix1[px]];
            float top = v00*(1.0f-wx) + v01*wx;
            float bot = v10*(1.0f-wx) + v11*wx;
            val = top*(1.0f-wy) + bot*wy;
        }
        trow[e] = val + pe[e];
    }
}

// ---------- Stage 3: gt = t @ W^T, M=200 N=2700 K=2700 ----------
// BM=40 (5 exact M-tiles), BN=128, 256 thr (tx 0..31, ty 0..7).
// A stored pre-duplicated {a,a} in smem: no movs in the inner loop.
__global__ void __launch_bounds__(256) gemm_kernel(
    const float* __restrict__ Wg, const float* __restrict__ Wa)
{
    const int v = blockIdx.z;
    const float* __restrict__ A = d_t  + (size_t)v * 200 * EMBED;
    const float* __restrict__ B = v ? Wa : Wg;
    float* __restrict__ C = d_gt + (size_t)v * 200 * EMBED;

    const int row0 = blockIdx.y * 40;      // 5*40=200, always in-range
    const int col0 = blockIdx.x * 128;

    __shared__ float2 AsD[40][33];
    __shared__ float  Bs[32][130];

    int tid = threadIdx.x;
    int tx = tid & 31, ty = tid >> 5;

    unsigned long long acc[5][2];
#pragma unroll
    for (int i = 0; i < 5; i++) { acc[i][0] = 0ull; acc[i][1] = 0ull; }

    float aReg[5], bReg[16];

    auto loadTile = [&](int k0) {
#pragma unroll
        for (int l = 0; l < 5; l++) {
            int idx = tid + l*256; int r = idx >> 5, kk = idx & 31;
            int gk = k0 + kk;
            aReg[l] = (gk < EMBED) ? A[(size_t)(row0 + r)*EMBED + gk] : 0.0f;
        }
#pragma unroll
        for (int l = 0; l < 16; l++) {
            int idx = tid + l*256; int r = idx >> 5, kk = idx & 31;
            int gc = col0 + r, gk = k0 + kk;
            bReg[l] = (gc < EMBED && gk < EMBED) ? B[(size_t)gc*EMBED + gk] : 0.0f;
        }
    };
    auto storeTile = [&]() {
#pragma unroll
        for (int l = 0; l < 5; l++) {
            int idx = tid + l*256;
            AsD[idx >> 5][idx & 31] = make_float2(aReg[l], aReg[l]);
        }
#pragma unroll
        for (int l = 0; l < 16; l++) {
            int idx = tid + l*256;
            Bs[idx & 31][idx >> 5] = bReg[l];
        }
    };

    loadTile(0); storeTile(); __syncthreads();

    const int NT = (EMBED + 31) / 32;  // 85
    for (int t = 0; t < NT; t++) {
        if (t + 1 < NT) loadTile((t + 1) * 32);
#pragma unroll 8
        for (int kk = 0; kk < 32; kk++) {
            unsigned long long bp[2];
            bp[0] = *reinterpret_cast<const unsigned long long*>(&Bs[kk][2*tx]);
            bp[1] = *reinterpret_cast<const unsigned long long*>(&Bs[kk][2*tx + 64]);
#pragma unroll
            for (int i = 0; i < 5; i++) {
                unsigned long long av =
                    *reinterpret_cast<const unsigned long long*>(&AsD[ty + 8*i][kk]);
                asm("fma.rn.f32x2 %0, %1, %2, %0;" : "+l"(acc[i][0]) : "l"(av), "l"(bp[0]));
                asm("fma.rn.f32x2 %0, %1, %2, %0;" : "+l"(acc[i][1]) : "l"(av), "l"(bp[1]));
            }
        }
        __syncthreads();
        if (t + 1 < NT) { storeTile(); __syncthreads(); }
    }

#pragma unroll
    for (int i = 0; i < 5; i++) {
        int gr = row0 + ty + 8*i;
#pragma unroll
        for (int p = 0; p < 2; p++) {
            int gc = col0 + 2*tx + 64*p;
            if (gc < EMBED) {
                float2 val;
                val.x = __uint_as_float((unsigned)(acc[i][p] & 0xffffffffu));
                val.y = __uint_as_float((unsigned)(acc[i][p] >> 32));
                *reinterpret_cast<float2*>(&C[(size_t)gr*EMBED + gc]) = val;
            }
        }
    }
}

// ---------- Stage 4: sim partials, split over e-chunks ----------
// grid (NCH, 2). e-major smem [ECH][112]: rows 100..111 are in-bounds padding
// (garbage values feed only accumulators that are never stored).
__global__ void __launch_bounds__(256) sim_kernel()
{
    int ch = blockIdx.x, b2 = blockIdx.y;
    __shared__ float Gs [ECH][112];
    __shared__ float As2[ECH][112];

    int tid = threadIdx.x;
    int e0 = ch * ECH;
    for (int l = tid; l < 100 * ECH; l += 256) {
        int r = l / ECH, e = l - r * ECH;
        Gs [e][r] = d_gt[(size_t)(      b2*100 + r)*EMBED + e0 + e];
        As2[e][r] = d_gt[(size_t)(200 + b2*100 + r)*EMBED + e0 + e];
    }
    __syncthreads();

    int tx = tid & 15, ty = tid >> 4;
    int nq = (ty < 4) ? 7 : 6;
    int nk = (tx < 4) ? 7 : 6;

    float acc[7][7];
#pragma unroll
    for (int i = 0; i < 7; i++)
#pragma unroll
        for (int j = 0; j < 7; j++) acc[i][j] = 0.0f;

    for (int e = 0; e < ECH; e++) {
        float ga[7], aa[7];
#pragma unroll
        for (int i = 0; i < 7; i++) ga[i] = Gs [e][ty + 16*i];  // <=111, in-bounds
#pragma unroll
        for (int j = 0; j < 7; j++) aa[j] = As2[e][tx + 16*j];
#pragma unroll
        for (int i = 0; i < 7; i++)
#pragma unroll
            for (int j = 0; j < 7; j++) acc[i][j] += ga[i] * aa[j];
    }

    float* o = &d_simp[(size_t)(ch*2 + b2) * 100 * 100];
    for (int i = 0; i < nq; i++)
        for (int j = 0; j < nk; j++)
            o[(tx + 16*j)*100 + (ty + 16*i)] = acc[i][j];   // [k][q]
}

// ---------- Stage 5: reduce partials + softmax over q ----------
__global__ void __launch_bounds__(128) softmax_kernel(float* __restrict__ out)
{
    int k = blockIdx.x, b2 = blockIdx.y, t = threadIdx.x;
    __shared__ float wr[4];
    __shared__ float bval;
    const float rscale = 0.051031036307982884f;   // 1/sqrt(384)

    float v = -3.4e38f;
    if (t < 100) {
        float s = 0.0f;
#pragma unroll 5
        for (int ch = 0; ch < NCH; ch++)
            s += d_simp[(size_t)((ch*2 + b2)*100 + k)*100 + t];
        v = s * rscale;
    }

    float m = v;
#pragma unroll
    for (int off = 16; off > 0; off >>= 1)
        m = fmaxf(m, __shfl_down_sync(0xffffffffu, m, off));
    if ((t & 31) == 0) wr[t >> 5] = m;
    __syncthreads();
    if (t == 0) bval = fmaxf(fmaxf(wr[0], wr[1]), fmaxf(wr[2], wr[3]));
    __syncthreads();
    float mx = bval;

    float e = (t < 100) ? expf(v - mx) : 0.0f;
    float s = e;
#pragma unroll
    for (int off = 16; off > 0; off >>= 1)
        s += __shfl_down_sync(0xffffffffu, s, off);
    if ((t & 31) == 0) wr[t >> 5] = s;
    __syncthreads();
    if (t == 0) bval = wr[0] + wr[1] + wr[2] + wr[3];
    __syncthreads();

    if (t < 100)
        out[(b2*100 + t)*100 + k] = e / bval;
}

// ---------- launch ----------
extern "C" void kernel_launch(void* const* d_in, const int* in_sizes, int n_in,
                              void* d_out, int out_size)
{
    const float* g_samples = (const float*)d_in[0];
    const float* a_samples = (const float*)d_in[1];
    const float* g_logits  = (const float*)d_in[2];
    const float* a_logits  = (const float*)d_in[3];
    const float* g_boxes   = (const float*)d_in[4];
    const float* a_boxes   = (const float*)d_in[5];
    const float* W_ground  = (const float*)d_in[6];
    const float* W_aerial  = (const float*)d_in[7];
    const float* pos_enc   = (const float*)d_in[8];
    float* out = (float*)d_out;

    topk_kernel<<<dim3(2, 2), 1024>>>(g_logits, a_logits, g_boxes, a_boxes);
    roi_kernel<<<dim3(200, 2), 256>>>(g_samples, a_samples, pos_enc);
    gemm_kernel<<<dim3(22, 5, 2), 256>>>(W_ground, W_aerial);
    sim_kernel<<<dim3(NCH, 2), 256>>>();
    softmax_kernel<<<dim3(100, 2), 128>>>(out);
}

// round 10
// speedup vs baseline: 2.7551x; 1.7677x over previous
#include <cuda_runtime.h>
#include <cuda_bf16.h>
#include <cstdint>

#define IMG 1024
#define EMBED 2700
#define ECH 54            // sim e-chunk (50 chunks * 54 = 2700)
#define NCH 50

// device scratch (no cudaMalloc allowed)
__device__ float d_boxes_px[2 * 2 * 100 * 4];   // [view][batch][slot][xyxy px]
__device__ float d_t [2 * 200 * EMBED];         // [view][row][e]
__device__ float d_gt[2 * 200 * EMBED];         // after Linear
__device__ float d_simp[NCH * 2 * 100 * 100];   // partial sims [ch][b][k][q]

// ---------- Stage 1: top-100 via histogram select + small bitonic ----------
__device__ __forceinline__ unsigned int prob_key(float x) {
    float p = 1.0f / (1.0f + expf(-x));
    return __float_as_uint(p);
}

__global__ void __launch_bounds__(1024) topk_kernel(
    const float* __restrict__ gl, const float* __restrict__ al,
    const float* __restrict__ gbx, const float* __restrict__ abx)
{
    int b = blockIdx.x, v = blockIdx.y;
    const float* logits = (v ? al : gl) + b * 6000;
    const float* boxes  = (v ? abx : gbx) + b * 300 * 4;
    int tid = threadIdx.x;

    __shared__ unsigned int hist[256];
    __shared__ int sT, scnt;
    __shared__ unsigned long long cand[4096];

    if (tid < 256) hist[tid] = 0u;
    __syncthreads();

    for (int i = tid; i < 6000; i += 1024)
        atomicAdd(&hist[prob_key(logits[i]) >> 22], 1u);
    __syncthreads();

    if (tid == 0) {
        unsigned int cum = 0; int T = 0;
        for (int bb = 255; bb >= 0; bb--) {
            cum += hist[bb];
            if (cum >= 100u) { T = bb; break; }
        }
        sT = T; scnt = 0;
    }
    __syncthreads();
    int T = sT;

    for (int i = tid; i < 6000; i += 1024) {
        unsigned int key = prob_key(logits[i]);
        if ((int)(key >> 22) >= T) {
            int pos = atomicAdd(&scnt, 1);
            if (pos < 4096)
                cand[pos] = (((unsigned long long)(0xFFFFFFFFu ^ key)) << 16)
                            | (unsigned long long)i;
        }
    }
    __syncthreads();

    int n = min(scnt, 4096);
    int n2 = 128;
    while (n2 < n) n2 <<= 1;

    for (int i = n + tid; i < n2; i += 1024) cand[i] = ~0ull;
    __syncthreads();

    for (int k = 2; k <= n2; k <<= 1)
        for (int j = k >> 1; j > 0; j >>= 1) {
            for (int i = tid; i < n2; i += 1024) {
                int ixj = i ^ j;
                if (ixj > i) {
                    unsigned long long a = cand[i], bb2 = cand[ixj];
                    bool up = ((i & k) == 0);
                    if ((a > bb2) == up) { cand[i] = bb2; cand[ixj] = a; }
                }
            }
            __syncthreads();
        }

    if (tid < 100) {
        int idx = (int)(cand[tid] & 0xFFFFull);
        int q = idx / 20;
        float cx = boxes[q*4+0], cy = boxes[q*4+1];
        float w  = boxes[q*4+2], h  = boxes[q*4+3];
        float* o = &d_boxes_px[((v*2 + b)*100 + tid)*4];
        o[0] = (cx - 0.5f*w) * 1024.0f;  o[1] = (cy - 0.5f*h) * 1024.0f;
        o[2] = (cx + 0.5f*w) * 1024.0f;  o[3] = (cy + 0.5f*h) * 1024.0f;
    }
}

// ---------- Stage 2: ROI bilinear 30x30 + interleave + pos_enc ----------
__global__ void __launch_bounds__(256) roi_kernel(
    const float* __restrict__ g_img, const float* __restrict__ a_img,
    const float* __restrict__ pos_enc)
{
    int m = blockIdx.x, v = blockIdx.y;
    const float* img = v ? a_img : g_img;
    int b = m & 1, kslot = m >> 1, k2 = m % 100;
    int tid = threadIdx.x;

    const float* bx = &d_boxes_px[((v*2 + b)*100 + kslot)*4];
    float x0 = rintf(bx[0]), y0 = rintf(bx[1]);
    float x1 = rintf(bx[2]), y1 = rintf(bx[3]);
    float w = x1 - x0, h = y1 - y0;
    bool valid = (w > 0.0f) && (h > 0.0f);

    __shared__ int   iy0[30], iy1[30], ix0[30], ix1[30];
    __shared__ float fwy[30], fwx[30];
    if (tid < 30) {
        float g = (float)tid + 0.5f;
        float sy = fminf(fmaxf(g * h / 30.0f - 0.5f, 0.0f), fmaxf(h - 1.0f, 0.0f));
        float ay = y0 + sy, yf = floorf(ay);
        fwy[tid] = ay - yf;
        iy0[tid] = (int)fminf(fmaxf(yf,        0.0f), 1023.0f);
        iy1[tid] = (int)fminf(fmaxf(yf + 1.0f, 0.0f), 1023.0f);
        float sx = fminf(fmaxf(g * w / 30.0f - 0.5f, 0.0f), fmaxf(w - 1.0f, 0.0f));
        float ax = x0 + sx, xf = floorf(ax);
        fwx[tid] = ax - xf;
        ix0[tid] = (int)fminf(fmaxf(xf,        0.0f), 1023.0f);
        ix1[tid] = (int)fminf(fmaxf(xf + 1.0f, 0.0f), 1023.0f);
    }
    __syncthreads();

    float* trow = &d_t[((size_t)(v*200 + m)) * EMBED];
    const float* pe = &pos_enc[(size_t)k2 * EMBED];
    for (int e = tid; e < EMBED; e += 256) {
        float val = 0.0f;
        if (valid) {
            int c = e / 900, r = e - c*900, py = r / 30, px = r - py*30;
            const float* ip = img + ((size_t)(b*3 + c) << 20);
            float wy = fwy[py], wx = fwx[px];
            const float* r0p = ip + iy0[py]*IMG;
            const float* r1p = ip + iy1[py]*IMG;
            float v00 = r0p[ix0[px]], v01 = r0p[ix1[px]];
            float v10 = r1p[ix0[px]], v11 = r1p[ix1[px]];
            float top = v00*(1.0f-wx) + v01*wx;
            float bot = v10*(1.0f-wx) + v11*wx;
            val = top*(1.0f-wy) + bot*wy;
        }
        trow[e] = val + pe[e];
    }
}

// ---------- Stage 3: gt = t @ W^T via mma.sync bf16 hi/lo split ----------
// BM=128, BN=128, 512 thr (16 warps 4x4; warp tile 32x32). K chunks of 32.
// C = Ah*Bh + Ah*Bl + Al*Bh accumulated in fp32 (error ~2^-16).
#define KC 32
#define LDP 40   // padded row stride (bf16 elems): 80B -> conflict-free ldmatrix

__device__ __forceinline__ void ldm_x4(uint32_t& r0, uint32_t& r1, uint32_t& r2, uint32_t& r3,
                                       uint32_t addr) {
    asm volatile("ldmatrix.sync.aligned.m8n8.x4.shared.b16 {%0,%1,%2,%3}, [%4];"
                 : "=r"(r0), "=r"(r1), "=r"(r2), "=r"(r3) : "r"(addr));
}
__device__ __forceinline__ void ldm_x2(uint32_t& r0, uint32_t& r1, uint32_t addr) {
    asm volatile("ldmatrix.sync.aligned.m8n8.x2.shared.b16 {%0,%1}, [%2];"
                 : "=r"(r0), "=r"(r1) : "r"(addr));
}
__device__ __forceinline__ void mma_bf16(float* c, const uint32_t* a, const uint32_t* b) {
    asm volatile(
        "mma.sync.aligned.m16n8k16.row.col.f32.bf16.bf16.f32 "
        "{%0,%1,%2,%3}, {%4,%5,%6,%7}, {%8,%9}, {%0,%1,%2,%3};"
        : "+f"(c[0]), "+f"(c[1]), "+f"(c[2]), "+f"(c[3])
        : "r"(a[0]), "r"(a[1]), "r"(a[2]), "r"(a[3]), "r"(b[0]), "r"(b[1]));
}
__device__ __forceinline__ uint32_t smem_u32(const void* p) {
    uint32_t a;
    asm("{ .reg .u64 t; cvta.to.shared.u64 t, %1; cvt.u32.u64 %0, t; }" : "=r"(a) : "l"(p));
    return a;
}
__device__ __forceinline__ uint2 split4(float4 x) {
    __nv_bfloat16 h0 = __float2bfloat16(x.x), h1 = __float2bfloat16(x.y);
    __nv_bfloat16 h2 = __float2bfloat16(x.z), h3 = __float2bfloat16(x.w);
    __nv_bfloat162 a = __halves2bfloat162(h0, h1), b = __halves2bfloat162(h2, h3);
    return make_uint2(*(uint32_t*)&a, *(uint32_t*)&b);
}
__device__ __forceinline__ uint2 split4lo(float4 x) {
    __nv_bfloat16 h0 = __float2bfloat16(x.x), h1 = __float2bfloat16(x.y);
    __nv_bfloat16 h2 = __float2bfloat16(x.z), h3 = __float2bfloat16(x.w);
    __nv_bfloat16 l0 = __float2bfloat16(x.x - __bfloat162float(h0));
    __nv_bfloat16 l1 = __float2bfloat16(x.y - __bfloat162float(h1));
    __nv_bfloat16 l2 = __float2bfloat16(x.z - __bfloat162float(h2));
    __nv_bfloat16 l3 = __float2bfloat16(x.w - __bfloat162float(h3));
    __nv_bfloat162 a = __halves2bfloat162(l0, l1), b = __halves2bfloat162(l2, l3);
    return make_uint2(*(uint32_t*)&a, *(uint32_t*)&b);
}

__global__ void __launch_bounds__(512, 1) hmma_gemm_kernel(
    const float* __restrict__ Wg, const float* __restrict__ Wa)
{
    const int v = blockIdx.z;
    const int row0  = blockIdx.y * 128;
    const int ncol0 = blockIdx.x * 128;
    const float* __restrict__ A = d_t + (size_t)v * 200 * EMBED;
    const float* __restrict__ B = v ? Wa : Wg;
    float* __restrict__ C = d_gt + (size_t)v * 200 * EMBED;

    __shared__ __nv_bfloat16 Ah[128][LDP], Al[128][LDP];
    __shared__ __nv_bfloat16 Bh[128][LDP], Bl[128][LDP];

    int tid = threadIdx.x;
    int wid = tid >> 5, lane = tid & 31;
    int wm = wid >> 2, wn = wid & 3;         // 4x4 warp grid

    float acc[2][4][4];
#pragma unroll
    for (int i = 0; i < 2; i++)
#pragma unroll
        for (int j = 0; j < 4; j++)
#pragma unroll
            for (int p = 0; p < 4; p++) acc[i][j][p] = 0.0f;

    float4 aPre[2], bPre[2];

    auto loadTile = [&](int c) {
        int k0 = c * KC;
#pragma unroll
        for (int l = 0; l < 2; l++) {
            int g = tid + l * 512;
            int r = g >> 3, c4 = g & 7;       // 8 float4 per 32-col row
            int gr = row0 + r, gc = k0 + c4 * 4;
            float4 x = make_float4(0.f, 0.f, 0.f, 0.f);
            if (gr < 200 && gc < EMBED) x = *(const float4*)(A + (size_t)gr * EMBED + gc);
            aPre[l] = x;
            int gr2 = ncol0 + r;
            float4 y = make_float4(0.f, 0.f, 0.f, 0.f);
            if (gr2 < EMBED && gc < EMBED) y = *(const float4*)(B + (size_t)gr2 * EMBED + gc);
            bPre[l] = y;
        }
    };
    auto storeTile = [&]() {
#pragma unroll
        for (int l = 0; l < 2; l++) {
            int g = tid + l * 512;
            int r = g >> 3, c4 = g & 7;
            *(uint2*)&Ah[r][c4 * 4] = split4(aPre[l]);
            *(uint2*)&Al[r][c4 * 4] = split4lo(aPre[l]);
            *(uint2*)&Bh[r][c4 * 4] = split4(bPre[l]);
            *(uint2*)&Bl[r][c4 * 4] = split4lo(bPre[l]);
        }
    };

    uint32_t sAh = smem_u32(Ah), sAl = smem_u32(Al);
    uint32_t sBh = smem_u32(Bh), sBl = smem_u32(Bl);

    const int NCHK = (EMBED + KC - 1) / KC;   // 85
    loadTile(0); storeTile(); __syncthreads();

    for (int c = 0; c < NCHK; c++) {
        if (c + 1 < NCHK) loadTile(c + 1);

#pragma unroll
        for (int ks = 0; ks < 2; ks++) {
            int k0 = ks * 16;
            // A frag lane addressing
            int sub = lane >> 3, ri = lane & 7;
            uint32_t ah[2][4], al[2][4], bh[4][2], bl[4][2];
#pragma unroll
            for (int im = 0; im < 2; im++) {
                int m0 = wm * 32 + im * 16;
                uint32_t off = ((uint32_t)((m0 + (sub & 1) * 8 + ri) * LDP
                                           + k0 + (sub >> 1) * 8)) * 2;
                ldm_x4(ah[im][0], ah[im][1], ah[im][2], ah[im][3], sAh + off);
                ldm_x4(al[im][0], al[im][1], al[im][2], al[im][3], sAl + off);
            }
#pragma unroll
            for (int jn = 0; jn < 4; jn++) {
                int n0 = wn * 32 + jn * 8;
                uint32_t off = ((uint32_t)((n0 + ri) * LDP + k0 + sub * 8)) * 2; // lanes 0-15 used
                ldm_x2(bh[jn][0], bh[jn][1], sBh + off);
                ldm_x2(bl[jn][0], bl[jn][1], sBl + off);
            }
#pragma unroll
            for (int im = 0; im < 2; im++)
#pragma unroll
                for (int jn = 0; jn < 4; jn++) {
                    mma_bf16(acc[im][jn], ah[im], bh[jn]);
                    mma_bf16(acc[im][jn], ah[im], bl[jn]);
                    mma_bf16(acc[im][jn], al[im], bh[jn]);
                }
        }
        __syncthreads();
        if (c + 1 < NCHK) { storeTile(); __syncthreads(); }
    }

    // epilogue: c0,c1 -> row m+lane/4 ; c2,c3 -> row m+8+lane/4 ; cols n+(lane%4)*2
#pragma unroll
    for (int im = 0; im < 2; im++) {
        int mbase = row0 + wm * 32 + im * 16 + (lane >> 2);
#pragma unroll
        for (int jn = 0; jn < 4; jn++) {
            int n = ncol0 + wn * 32 + jn * 8 + (lane & 3) * 2;
            if (n < EMBED) {
                if (mbase < 200)
                    *(float2*)(C + (size_t)mbase * EMBED + n) =
                        make_float2(acc[im][jn][0], acc[im][jn][1]);
                if (mbase + 8 < 200)
                    *(float2*)(C + (size_t)(mbase + 8) * EMBED + n) =
                        make_float2(acc[im][jn][2], acc[im][jn][3]);
            }
        }
    }
}

// ---------- Stage 4: sim partials, split over e-chunks ----------
__global__ void __launch_bounds__(256) sim_kernel()
{
    int ch = blockIdx.x, b2 = blockIdx.y;
    __shared__ float Gs [ECH][112];
    __shared__ float As2[ECH][112];

    int tid = threadIdx.x;
    int e0 = ch * ECH;
    for (int l = tid; l < 100 * ECH; l += 256) {
        int r = l / ECH, e = l - r * ECH;
        Gs [e][r] = d_gt[(size_t)(      b2*100 + r)*EMBED + e0 + e];
        As2[e][r] = d_gt[(size_t)(200 + b2*100 + r)*EMBED + e0 + e];
    }
    __syncthreads();

    int tx = tid & 15, ty = tid >> 4;
    int nq = (ty < 4) ? 7 : 6;
    int nk = (tx < 4) ? 7 : 6;

    float acc[7][7];
#pragma unroll
    for (int i = 0; i < 7; i++)
#pragma unroll
        for (int j = 0; j < 7; j++) acc[i][j] = 0.0f;

    for (int e = 0; e < ECH; e++) {
        float ga[7], aa[7];
#pragma unroll
        for (int i = 0; i < 7; i++) ga[i] = Gs [e][ty + 16*i];
#pragma unroll
        for (int j = 0; j < 7; j++) aa[j] = As2[e][tx + 16*j];
#pragma unroll
        for (int i = 0; i < 7; i++)
#pragma unroll
            for (int j = 0; j < 7; j++) acc[i][j] += ga[i] * aa[j];
    }

    float* o = &d_simp[(size_t)(ch*2 + b2) * 100 * 100];
    for (int i = 0; i < nq; i++)
        for (int j = 0; j < nk; j++)
            o[(tx + 16*j)*100 + (ty + 16*i)] = acc[i][j];
}

// ---------- Stage 5: reduce partials + softmax over q ----------
__global__ void __launch_bounds__(128) softmax_kernel(float* __restrict__ out)
{
    int k = blockIdx.x, b2 = blockIdx.y, t = threadIdx.x;
    __shared__ float wr[4];
    __shared__ float bval;
    const float rscale = 0.051031036307982884f;   // 1/sqrt(384)

    float v = -3.4e38f;
    if (t < 100) {
        float s = 0.0f;
#pragma unroll 5
        for (int ch = 0; ch < NCH; ch++)
            s += d_simp[(size_t)((ch*2 + b2)*100 + k)*100 + t];
        v = s * rscale;
    }

    float m = v;
#pragma unroll
    for (int off = 16; off > 0; off >>= 1)
        m = fmaxf(m, __shfl_down_sync(0xffffffffu, m, off));
    if ((t & 31) == 0) wr[t >> 5] = m;
    __syncthreads();
    if (t == 0) bval = fmaxf(fmaxf(wr[0], wr[1]), fmaxf(wr[2], wr[3]));
    __syncthreads();
    float mx = bval;

    float e = (t < 100) ? expf(v - mx) : 0.0f;
    float s = e;
#pragma unroll
    for (int off = 16; off > 0; off >>= 1)
        s += __shfl_down_sync(0xffffffffu, s, off);
    if ((t & 31) == 0) wr[t >> 5] = s;
    __syncthreads();
    if (t == 0) bval = wr[0] + wr[1] + wr[2] + wr[3];
    __syncthreads();

    if (t < 100)
        out[(b2*100 + t)*100 + k] = e / bval;
}

// ---------- launch ----------
extern "C" void kernel_launch(void* const* d_in, const int* in_sizes, int n_in,
                              void* d_out, int out_size)
{
    const float* g_samples = (const float*)d_in[0];
    const float* a_samples = (const float*)d_in[1];
    const float* g_logits  = (const float*)d_in[2];
    const float* a_logits  = (const float*)d_in[3];
    const float* g_boxes   = (const float*)d_in[4];
    const float* a_boxes   = (const float*)d_in[5];
    const float* W_ground  = (const float*)d_in[6];
    const float* W_aerial  = (const float*)d_in[7];
    const float* pos_enc   = (const float*)d_in[8];
    float* out = (float*)d_out;

    topk_kernel<<<dim3(2, 2), 1024>>>(g_logits, a_logits, g_boxes, a_boxes);
    roi_kernel<<<dim3(200, 2), 256>>>(g_samples, a_samples, pos_enc);
    hmma_gemm_kernel<<<dim3(22, 2, 2), 512>>>(W_ground, W_aerial);
    sim_kernel<<<dim3(NCH, 2), 256>>>();
    softmax_kernel<<<dim3(100, 2), 128>>>(out);
}